// round 10
// baseline (speedup 1.0000x reference)
#include <cuda_runtime.h>
#include <math.h>

#define MAXV 100000

// Scratch (allocation-free rule: __device__ globals).
// g_feat: 4 float4 per node (64B stride; [3] pad):
//   [0] = {d00, da, db, dself}
//   [1] = {X, Y, PA, PB}
//   [2] = {RP, RQ, self1, self2}
__device__ float4 g_feat[MAXV * 4];
__device__ float4 g_acc[MAXV];   // {sum m0, sum mv1, sum mv2, degree}

// Shared weight layout
#define W_N00    0
#define W_N01    16
#define W_SELF0  48
#define W_N10    64
#define W_N11    96
#define W_SELF11 160

#define FB 128            // nodes per feat block (= threads per block)
#define ROWP 49           // padded row stride (floats); 49 mod 32 = 17 -> conflict-free

__global__ __launch_bounds__(FB) void feat_kernel(
    const float* __restrict__ x,
    const float* __restrict__ w_self0,
    const float* __restrict__ w_n00,
    const float* __restrict__ w_n10,
    const float* __restrict__ w_self11,
    const float* __restrict__ w_n01,
    const float* __restrict__ w_n11,
    int V)
{
    __shared__ float sw[192];
    __shared__ float sx[FB * ROWP];

    int t = threadIdx.x;
    // FB=128 < 192: must stride (R9 bug: plain `if (t<192)` left sw[128..191] garbage)
    for (int i = t; i < 192; i += FB) {
        float val;
        if      (i < 16)  val = w_n00[i];
        else if (i < 48)  val = w_n01[i - 16];
        else if (i < 64)  val = w_self0[i - 48];
        else if (i < 96)  val = w_n10[i - 64];
        else if (i < 160) val = w_n11[i - 96];
        else              val = w_self11[i - 160];
        sw[i] = val;
    }

    int vb = blockIdx.x * FB;
    int nodes = min(FB, V - vb);
    int nf4 = nodes * 12;                       // float4 count for this block

    // Coalesced staging: consecutive float4 across the block
    const float4* xg = (const float4*)(x + (size_t)vb * 48);
    for (int f = t; f < nf4; f += FB) {
        float4 val = xg[f];
        int fl   = f * 4;                       // float index within block
        int node = fl / 48;                     // float4 never crosses a row (48 % 4 == 0)
        int col  = fl - node * 48;
        float* d = &sx[node * ROWP + col];
        d[0] = val.x; d[1] = val.y; d[2] = val.z; d[3] = val.w;
    }
    __syncthreads();

    int v = vb + t;
    if (v >= V) return;
    const float* xr = &sx[t * ROWP];

    float d00 = 0.f, da = 0.f, db = 0.f, ds = 0.f;
#pragma unroll
    for (int c = 0; c < 16; c++) {
        float x0 = xr[c];
        d00 = fmaf(x0, sw[W_N00 + c], d00);
        da  = fmaf(x0, sw[W_N01 + 2 * c], da);
        db  = fmaf(x0, sw[W_N01 + 2 * c + 1], db);
        ds  = fmaf(x0, sw[W_SELF0 + c], ds);
    }

    float X = 0.f, Y = 0.f, PA = 0.f, PB = 0.f, RP = 0.f, RQ = 0.f, s1 = 0.f, s2 = 0.f;
#pragma unroll
    for (int c = 0; c < 16; c++) {
        float a = xr[16 + 2 * c];
        float b = xr[17 + 2 * c];
        float wa = sw[W_N10 + 2 * c],     wb = sw[W_N10 + 2 * c + 1];
        float p  = sw[W_N11 + 4 * c],     q  = sw[W_N11 + 4 * c + 1];
        float r  = sw[W_N11 + 4 * c + 2], s  = sw[W_N11 + 4 * c + 3];
        float sa = sw[W_SELF11 + 2 * c],  sb = sw[W_SELF11 + 2 * c + 1];
        X  = fmaf(a, wa,  fmaf(b, wb, X));
        Y  = fmaf(a, wb,  fmaf(-b, wa, Y));
        PA = fmaf(a, p,   fmaf(-b, q, PA));
        PB = fmaf(b, p,   fmaf(a, q, PB));
        RP = fmaf(a, r,   fmaf(b, s, RP));
        RQ = fmaf(a, s,   fmaf(-b, r, RQ));
        s1 = fmaf(a, sa,  fmaf(-b, sb, s1));
        s2 = fmaf(b, sa,  fmaf(a, sb, s2));
    }

    g_feat[4 * v + 0] = make_float4(d00, da, db, ds);
    g_feat[4 * v + 1] = make_float4(X, Y, PA, PB);
    g_feat[4 * v + 2] = make_float4(RP, RQ, s1, s2);
    g_acc[v] = make_float4(0.f, 0.f, 0.f, 0.f);
}

__device__ __forceinline__ void edge_math(float4 f0, float4 f1, float4 f2,
                                          float ang, float tr, int dst)
{
    float st, ct, sg, cg;
    __sincosf(ang, &st, &ct);
    __sincosf(tr,  &sg, &cg);
    float c2t = ct * ct - st * st;
    float s2t = 2.f * st * ct;

    float d1 = cg * f1.x + sg * f1.y;
    float d2 = sg * f1.x - cg * f1.y;
    float A  = cg * f1.z - sg * f1.w;
    float B  = sg * f1.z + cg * f1.w;
    float P  = cg * f2.x + sg * f2.y;
    float Q  = sg * f2.x - cg * f2.y;

    float m0  = f0.x + ct * d1 + st * d2;
    float mv1 = f0.y * ct - f0.z * st + A + c2t * P + s2t * Q;
    float mv2 = f0.y * st + f0.z * ct + B + s2t * P - c2t * Q;

    float4* addr = &g_acc[dst];
    asm volatile("red.global.add.v4.f32 [%0], {%1, %2, %3, %4};"
                 :: "l"(addr), "f"(m0), "f"(mv1), "f"(mv2), "f"(1.0f)
                 : "memory");
}

__global__ void edge_kernel(const int* __restrict__ ei,
                            const float* __restrict__ angles,
                            const float* __restrict__ transp,
                            int E)
{
    int i = blockIdx.x * blockDim.x + threadIdx.x;
    int e = 4 * i;
    if (e >= E) return;

    if (e + 3 < E) {
        // batched coalesced parameter loads (e % 4 == 0 -> 16B aligned)
        int4   sp = *(const int4*)(ei + e);
        int4   dp = *(const int4*)(ei + (size_t)E + e);
        float4 an = *(const float4*)(angles + e);
        float4 tp = *(const float4*)(transp + e);

        // issue all 12 gathers back-to-back for max MLP
        float4 a0 = g_feat[4 * sp.x + 0];
        float4 a1 = g_feat[4 * sp.x + 1];
        float4 a2 = g_feat[4 * sp.x + 2];
        float4 b0 = g_feat[4 * sp.y + 0];
        float4 b1 = g_feat[4 * sp.y + 1];
        float4 b2 = g_feat[4 * sp.y + 2];
        float4 c0 = g_feat[4 * sp.z + 0];
        float4 c1 = g_feat[4 * sp.z + 1];
        float4 c2 = g_feat[4 * sp.z + 2];
        float4 d0 = g_feat[4 * sp.w + 0];
        float4 d1 = g_feat[4 * sp.w + 1];
        float4 d2 = g_feat[4 * sp.w + 2];

        edge_math(a0, a1, a2, an.x, tp.x, dp.x);
        edge_math(b0, b1, b2, an.y, tp.y, dp.y);
        edge_math(c0, c1, c2, an.z, tp.z, dp.z);
        edge_math(d0, d1, d2, an.w, tp.w, dp.w);
    } else {
        for (int k = e; k < E; k++) {
            int src = ei[k];
            edge_math(g_feat[4 * src + 0], g_feat[4 * src + 1], g_feat[4 * src + 2],
                      angles[k], transp[k], ei[(size_t)E + k]);
        }
    }
}

__global__ void out_kernel(const float* __restrict__ e1,
                           const float* __restrict__ e2,
                           float* __restrict__ out,
                           int V)
{
    int v = blockIdx.x * blockDim.x + threadIdx.x;
    if (v >= V) return;

    float4 a  = g_acc[v];
    float inv = 1.0f / fmaxf(a.w, 1.0f);
    float4 f0 = g_feat[4 * v + 0];
    float4 f2 = g_feat[4 * v + 2];

    float mag = a.x * inv + f0.w;
    float t1  = a.y * inv + f2.z;
    float t2  = a.z * inv + f2.w;
    float scale = __fdividef(2.0f, 1.0f + __expf(-mag));

    float s1 = t1 * scale, s2 = t2 * scale;
    out[3 * v + 0] = s1 * e1[3 * v + 0] + s2 * e2[3 * v + 0];
    out[3 * v + 1] = s1 * e1[3 * v + 1] + s2 * e2[3 * v + 1];
    out[3 * v + 2] = s1 * e1[3 * v + 2] + s2 * e2[3 * v + 2];
}

extern "C" void kernel_launch(void* const* d_in, const int* in_sizes, int n_in,
                              void* d_out, int out_size)
{
    const float* x        = (const float*)d_in[0];
    const int*   ei       = (const int*)d_in[1];
    const float* angles   = (const float*)d_in[2];
    const float* transp   = (const float*)d_in[3];
    const float* e1       = (const float*)d_in[4];
    const float* e2       = (const float*)d_in[5];
    const float* w_self0  = (const float*)d_in[6];
    const float* w_n00    = (const float*)d_in[7];
    const float* w_n10    = (const float*)d_in[8];
    const float* w_self11 = (const float*)d_in[9];
    const float* w_n01    = (const float*)d_in[10];
    const float* w_n11    = (const float*)d_in[11];
    float* out = (float*)d_out;

    int V = in_sizes[0] / 48;
    int E = in_sizes[2];

    feat_kernel<<<(V + FB - 1) / FB, FB>>>(x, w_self0, w_n00, w_n10,
                                           w_self11, w_n01, w_n11, V);
    int quads = (E + 3) / 4;
    edge_kernel<<<(quads + 255) / 256, 256>>>(ei, angles, transp, E);
    out_kernel<<<(V + 255) / 256, 256>>>(e1, e2, out, V);
}

// round 12
// speedup vs baseline: 1.2438x; 1.2438x over previous
#include <cuda_runtime.h>
#include <cuda_fp16.h>
#include <math.h>

#define MAXV 100000

// Packed per-node record: 2 float4 (32 B, one L2 sector).
// rec0 = { d00 (f32), half2(da,db), half2(X,Y), half2(PA,PB) }   <- edge reads rec0 + rec1.x
// rec1 = { half2(RP,RQ), ds (f32), s1 (f32), s2 (f32) }          <- out reads rec1.y/z/w
__device__ float4 g_pack[MAXV * 2];
__device__ float4 g_acc[MAXV];   // {sum m0, sum mv1, sum mv2, degree}

__device__ __forceinline__ float pack2(float a, float b) {
    __half2 h = __floats2half2_rn(a, b);
    return __uint_as_float(*reinterpret_cast<unsigned*>(&h));
}
__device__ __forceinline__ float2 unpack2(float f) {
    unsigned u = __float_as_uint(f);
    __half2 h = *reinterpret_cast<__half2*>(&u);
    return __half22float2(h);
}

// Shared weight layout
#define W_N00    0
#define W_N01    16
#define W_SELF0  48
#define W_N10    64
#define W_N11    96
#define W_SELF11 160

#define FB 128            // nodes per feat block (= threads per block)
#define ROWP 49           // padded smem row stride; 49 mod 32 = 17 -> conflict-free

__global__ __launch_bounds__(FB, 8) void feat_kernel(
    const float* __restrict__ x,
    const float* __restrict__ w_self0,
    const float* __restrict__ w_n00,
    const float* __restrict__ w_n10,
    const float* __restrict__ w_self11,
    const float* __restrict__ w_n01,
    const float* __restrict__ w_n11,
    int V)
{
    __shared__ float sw[192];
    __shared__ float sx[FB * ROWP];

    int t = threadIdx.x;
    for (int i = t; i < 192; i += FB) {
        float val;
        if      (i < 16)  val = w_n00[i];
        else if (i < 48)  val = w_n01[i - 16];
        else if (i < 64)  val = w_self0[i - 48];
        else if (i < 96)  val = w_n10[i - 64];
        else if (i < 160) val = w_n11[i - 96];
        else              val = w_self11[i - 160];
        sw[i] = val;
    }

    int vb = blockIdx.x * FB;
    int nodes = min(FB, V - vb);
    int nf4 = nodes * 12;

    const float4* xg = (const float4*)(x + (size_t)vb * 48);
    for (int f = t; f < nf4; f += FB) {
        float4 val = xg[f];
        int fl   = f * 4;
        int node = fl / 48;                 // float4 never crosses a row (48 % 4 == 0)
        int col  = fl - node * 48;
        float* d = &sx[node * ROWP + col];
        d[0] = val.x; d[1] = val.y; d[2] = val.z; d[3] = val.w;
    }
    __syncthreads();

    int v = vb + t;
    if (v >= V) return;
    const float* xr = &sx[t * ROWP];

    float d00 = 0.f, da = 0.f, db = 0.f, ds = 0.f;
#pragma unroll
    for (int c = 0; c < 16; c++) {
        float x0 = xr[c];
        d00 = fmaf(x0, sw[W_N00 + c], d00);
        da  = fmaf(x0, sw[W_N01 + 2 * c], da);
        db  = fmaf(x0, sw[W_N01 + 2 * c + 1], db);
        ds  = fmaf(x0, sw[W_SELF0 + c], ds);
    }

    float X = 0.f, Y = 0.f, PA = 0.f, PB = 0.f, RP = 0.f, RQ = 0.f, s1 = 0.f, s2 = 0.f;
#pragma unroll
    for (int c = 0; c < 16; c++) {
        float a = xr[16 + 2 * c];
        float b = xr[17 + 2 * c];
        float wa = sw[W_N10 + 2 * c],     wb = sw[W_N10 + 2 * c + 1];
        float p  = sw[W_N11 + 4 * c],     q  = sw[W_N11 + 4 * c + 1];
        float r  = sw[W_N11 + 4 * c + 2], s  = sw[W_N11 + 4 * c + 3];
        float sa = sw[W_SELF11 + 2 * c],  sb = sw[W_SELF11 + 2 * c + 1];
        X  = fmaf(a, wa,  fmaf(b, wb, X));
        Y  = fmaf(a, wb,  fmaf(-b, wa, Y));
        PA = fmaf(a, p,   fmaf(-b, q, PA));
        PB = fmaf(b, p,   fmaf(a, q, PB));
        RP = fmaf(a, r,   fmaf(b, s, RP));
        RQ = fmaf(a, s,   fmaf(-b, r, RQ));
        s1 = fmaf(a, sa,  fmaf(-b, sb, s1));
        s2 = fmaf(b, sa,  fmaf(a, sb, s2));
    }

    g_pack[2 * v + 0] = make_float4(d00, pack2(da, db), pack2(X, Y), pack2(PA, PB));
    g_pack[2 * v + 1] = make_float4(pack2(RP, RQ), ds, s1, s2);
    g_acc[v] = make_float4(0.f, 0.f, 0.f, 0.f);
}

__device__ __forceinline__ void edge_math(float4 r0, float rpq_packed,
                                          float ang, float tr, int dst)
{
    float st, ct, sg, cg;
    __sincosf(ang, &st, &ct);
    __sincosf(tr,  &sg, &cg);
    float c2t = ct * ct - st * st;
    float s2t = 2.f * st * ct;

    float2 dab = unpack2(r0.y);
    float2 xy  = unpack2(r0.z);
    float2 pab = unpack2(r0.w);
    float2 rpq = unpack2(rpq_packed);

    float d1 = cg * xy.x + sg * xy.y;
    float d2 = sg * xy.x - cg * xy.y;
    float A  = cg * pab.x - sg * pab.y;
    float B  = sg * pab.x + cg * pab.y;
    float P  = cg * rpq.x + sg * rpq.y;
    float Q  = sg * rpq.x - cg * rpq.y;

    float m0  = r0.x + ct * d1 + st * d2;
    float mv1 = dab.x * ct - dab.y * st + A + c2t * P + s2t * Q;
    float mv2 = dab.x * st + dab.y * ct + B + s2t * P - c2t * Q;

    float4* addr = &g_acc[dst];
    asm volatile("red.global.add.v4.f32 [%0], {%1, %2, %3, %4};"
                 :: "l"(addr), "f"(m0), "f"(mv1), "f"(mv2), "f"(1.0f)
                 : "memory");
}

__global__ void edge_kernel(const int* __restrict__ ei,
                            const float* __restrict__ angles,
                            const float* __restrict__ transp,
                            int E)
{
    int i = blockIdx.x * blockDim.x + threadIdx.x;
    int e = 4 * i;
    if (e >= E) return;

    const float* pk = (const float*)g_pack;   // scalar view for the rpq word

    if (e + 3 < E) {
        int4   sp = *(const int4*)(ei + e);
        int4   dp = *(const int4*)(ei + (size_t)E + e);
        float4 an = *(const float4*)(angles + e);
        float4 tp = *(const float4*)(transp + e);

        // 8 gathers back-to-back (2 per edge, both in one 32B sector)
        float4 a0 = g_pack[2 * sp.x];
        float  a1 = pk[8 * sp.x + 4];
        float4 b0 = g_pack[2 * sp.y];
        float  b1 = pk[8 * sp.y + 4];
        float4 c0 = g_pack[2 * sp.z];
        float  c1 = pk[8 * sp.z + 4];
        float4 d0 = g_pack[2 * sp.w];
        float  d1 = pk[8 * sp.w + 4];

        edge_math(a0, a1, an.x, tp.x, dp.x);
        edge_math(b0, b1, an.y, tp.y, dp.y);
        edge_math(c0, c1, an.z, tp.z, dp.z);
        edge_math(d0, d1, an.w, tp.w, dp.w);
    } else {
        for (int k = e; k < E; k++) {
            int src = ei[k];
            edge_math(g_pack[2 * src], pk[8 * src + 4],
                      angles[k], transp[k], ei[(size_t)E + k]);
        }
    }
}

__global__ void out_kernel(const float* __restrict__ e1,
                           const float* __restrict__ e2,
                           float* __restrict__ out,
                           int V)
{
    int v = blockIdx.x * blockDim.x + threadIdx.x;
    if (v >= V) return;

    float4 a  = g_acc[v];
    float inv = 1.0f / fmaxf(a.w, 1.0f);
    float4 r1 = g_pack[2 * v + 1];     // {rpq, ds, s1, s2}

    float mag = a.x * inv + r1.y;
    float t1  = a.y * inv + r1.z;
    float t2  = a.z * inv + r1.w;
    float scale = __fdividef(2.0f, 1.0f + __expf(-mag));

    float s1 = t1 * scale, s2 = t2 * scale;
    out[3 * v + 0] = s1 * e1[3 * v + 0] + s2 * e2[3 * v + 0];
    out[3 * v + 1] = s1 * e1[3 * v + 1] + s2 * e2[3 * v + 1];
    out[3 * v + 2] = s1 * e1[3 * v + 2] + s2 * e2[3 * v + 2];
}

extern "C" void kernel_launch(void* const* d_in, const int* in_sizes, int n_in,
                              void* d_out, int out_size)
{
    const float* x        = (const float*)d_in[0];
    const int*   ei       = (const int*)d_in[1];
    const float* angles   = (const float*)d_in[2];
    const float* transp   = (const float*)d_in[3];
    const float* e1       = (const float*)d_in[4];
    const float* e2       = (const float*)d_in[5];
    const float* w_self0  = (const float*)d_in[6];
    const float* w_n00    = (const float*)d_in[7];
    const float* w_n10    = (const float*)d_in[8];
    const float* w_self11 = (const float*)d_in[9];
    const float* w_n01    = (const float*)d_in[10];
    const float* w_n11    = (const float*)d_in[11];
    float* out = (float*)d_out;

    int V = in_sizes[0] / 48;
    int E = in_sizes[2];

    // Raise L1/smem carveout so 8 blocks (26KB smem each) fit per SM.
    // Host-side attribute set: no allocation, no stream op -> capture-safe.
    static bool attr_done = false;
    if (!attr_done) {
        cudaFuncSetAttribute(feat_kernel,
                             cudaFuncAttributePreferredSharedMemoryCarveout, 100);
        attr_done = true;
    }

    feat_kernel<<<(V + FB - 1) / FB, FB>>>(x, w_self0, w_n00, w_n10,
                                           w_self11, w_n01, w_n11, V);
    int quads = (E + 3) / 4;
    edge_kernel<<<(quads + 255) / 256, 256>>>(ei, angles, transp, E);
    out_kernel<<<(V + 255) / 256, 256>>>(e1, e2, out, V);
}

// round 13
// speedup vs baseline: 1.2738x; 1.0241x over previous
#include <cuda_runtime.h>
#include <cuda_fp16.h>
#include <math.h>

#define MAXV 100000

// Packed per-node record: 2 float4 (32 B, one L2 sector).
// rec0 = { d00 (f32), half2(da,db), half2(X,Y), half2(PA,PB) }   <- edge reads rec0 + rec1.x
// rec1 = { half2(RP,RQ), ds (f32), s1 (f32), s2 (f32) }          <- out reads rec1.y/z/w
__device__ float4 g_pack[MAXV * 2];
__device__ float4 g_acc[MAXV];   // {sum m0, sum mv1, sum mv2, degree}

__device__ __forceinline__ float pack2(float a, float b) {
    __half2 h = __floats2half2_rn(a, b);
    return __uint_as_float(*reinterpret_cast<unsigned*>(&h));
}
__device__ __forceinline__ float2 unpack2(float f) {
    unsigned u = __float_as_uint(f);
    __half2 h = *reinterpret_cast<__half2*>(&u);
    return __half22float2(h);
}

// Shared weight layout
#define W_N00    0
#define W_N01    16
#define W_SELF0  48
#define W_N10    64
#define W_N11    96
#define W_SELF11 160

#define FB 128            // nodes per feat block (= threads per block)
#define ROWP 49           // padded smem row stride; 49 mod 32 = 17 -> conflict-free

__global__ __launch_bounds__(FB, 8) void feat_kernel(
    const float* __restrict__ x,
    const float* __restrict__ w_self0,
    const float* __restrict__ w_n00,
    const float* __restrict__ w_n10,
    const float* __restrict__ w_self11,
    const float* __restrict__ w_n01,
    const float* __restrict__ w_n11,
    int V)
{
    __shared__ float sw[192];
    __shared__ float sx[FB * ROWP];

    int t = threadIdx.x;
    for (int i = t; i < 192; i += FB) {
        float val;
        if      (i < 16)  val = w_n00[i];
        else if (i < 48)  val = w_n01[i - 16];
        else if (i < 64)  val = w_self0[i - 48];
        else if (i < 96)  val = w_n10[i - 64];
        else if (i < 160) val = w_n11[i - 96];
        else              val = w_self11[i - 160];
        sw[i] = val;
    }

    int vb = blockIdx.x * FB;
    int nodes = min(FB, V - vb);
    const float4* xg = (const float4*)(x + (size_t)vb * 48);

    if (nodes == FB) {
        // Full block: compile-time trip count -> all 12 LDG.128 issued
        // back-to-back (MLP=12) before any STS.
        float4 r[12];
#pragma unroll
        for (int j = 0; j < 12; j++) r[j] = xg[t + j * FB];
#pragma unroll
        for (int j = 0; j < 12; j++) {
            int fl   = (t + j * FB) * 4;
            int node = fl / 48;             // float4 never crosses a row (48 % 4 == 0)
            int col  = fl - node * 48;
            float* d = &sx[node * ROWP + col];
            d[0] = r[j].x; d[1] = r[j].y; d[2] = r[j].z; d[3] = r[j].w;
        }
    } else {
        int nf4 = nodes * 12;
        for (int f = t; f < nf4; f += FB) {
            float4 val = xg[f];
            int fl   = f * 4;
            int node = fl / 48;
            int col  = fl - node * 48;
            float* d = &sx[node * ROWP + col];
            d[0] = val.x; d[1] = val.y; d[2] = val.z; d[3] = val.w;
        }
    }
    __syncthreads();

    int v = vb + t;
    if (v >= V) return;
    const float* xr = &sx[t * ROWP];

    float d00 = 0.f, da = 0.f, db = 0.f, ds = 0.f;
#pragma unroll
    for (int c = 0; c < 16; c++) {
        float x0 = xr[c];
        d00 = fmaf(x0, sw[W_N00 + c], d00);
        da  = fmaf(x0, sw[W_N01 + 2 * c], da);
        db  = fmaf(x0, sw[W_N01 + 2 * c + 1], db);
        ds  = fmaf(x0, sw[W_SELF0 + c], ds);
    }

    float X = 0.f, Y = 0.f, PA = 0.f, PB = 0.f, RP = 0.f, RQ = 0.f, s1 = 0.f, s2 = 0.f;
#pragma unroll
    for (int c = 0; c < 16; c++) {
        float a = xr[16 + 2 * c];
        float b = xr[17 + 2 * c];
        float wa = sw[W_N10 + 2 * c],     wb = sw[W_N10 + 2 * c + 1];
        float p  = sw[W_N11 + 4 * c],     q  = sw[W_N11 + 4 * c + 1];
        float r  = sw[W_N11 + 4 * c + 2], s  = sw[W_N11 + 4 * c + 3];
        float sa = sw[W_SELF11 + 2 * c],  sb = sw[W_SELF11 + 2 * c + 1];
        X  = fmaf(a, wa,  fmaf(b, wb, X));
        Y  = fmaf(a, wb,  fmaf(-b, wa, Y));
        PA = fmaf(a, p,   fmaf(-b, q, PA));
        PB = fmaf(b, p,   fmaf(a, q, PB));
        RP = fmaf(a, r,   fmaf(b, s, RP));
        RQ = fmaf(a, s,   fmaf(-b, r, RQ));
        s1 = fmaf(a, sa,  fmaf(-b, sb, s1));
        s2 = fmaf(b, sa,  fmaf(a, sb, s2));
    }

    g_pack[2 * v + 0] = make_float4(d00, pack2(da, db), pack2(X, Y), pack2(PA, PB));
    g_pack[2 * v + 1] = make_float4(pack2(RP, RQ), ds, s1, s2);
    g_acc[v] = make_float4(0.f, 0.f, 0.f, 0.f);
}

__device__ __forceinline__ void edge_math(float4 r0, float rpq_packed,
                                          float ang, float tr, int dst)
{
    float st, ct, sg, cg;
    __sincosf(ang, &st, &ct);
    __sincosf(tr,  &sg, &cg);
    float c2t = ct * ct - st * st;
    float s2t = 2.f * st * ct;

    float2 dab = unpack2(r0.y);
    float2 xy  = unpack2(r0.z);
    float2 pab = unpack2(r0.w);
    float2 rpq = unpack2(rpq_packed);

    float d1 = cg * xy.x + sg * xy.y;
    float d2 = sg * xy.x - cg * xy.y;
    float A  = cg * pab.x - sg * pab.y;
    float B  = sg * pab.x + cg * pab.y;
    float P  = cg * rpq.x + sg * rpq.y;
    float Q  = sg * rpq.x - cg * rpq.y;

    float m0  = r0.x + ct * d1 + st * d2;
    float mv1 = dab.x * ct - dab.y * st + A + c2t * P + s2t * Q;
    float mv2 = dab.x * st + dab.y * ct + B + s2t * P - c2t * Q;

    float4* addr = &g_acc[dst];
    asm volatile("red.global.add.v4.f32 [%0], {%1, %2, %3, %4};"
                 :: "l"(addr), "f"(m0), "f"(mv1), "f"(mv2), "f"(1.0f)
                 : "memory");
}

__global__ void edge_kernel(const int* __restrict__ ei,
                            const float* __restrict__ angles,
                            const float* __restrict__ transp,
                            int E)
{
    int i = blockIdx.x * blockDim.x + threadIdx.x;
    int e = 4 * i;
    if (e >= E) return;

    const float* pk = (const float*)g_pack;   // scalar view for the rpq word

    if (e + 3 < E) {
        int4   sp = *(const int4*)(ei + e);
        int4   dp = *(const int4*)(ei + (size_t)E + e);
        float4 an = *(const float4*)(angles + e);
        float4 tp = *(const float4*)(transp + e);

        // 8 gathers back-to-back (2 per edge, both in one 32B sector)
        float4 a0 = g_pack[2 * sp.x];
        float  a1 = pk[8 * sp.x + 4];
        float4 b0 = g_pack[2 * sp.y];
        float  b1 = pk[8 * sp.y + 4];
        float4 c0 = g_pack[2 * sp.z];
        float  c1 = pk[8 * sp.z + 4];
        float4 d0 = g_pack[2 * sp.w];
        float  d1 = pk[8 * sp.w + 4];

        edge_math(a0, a1, an.x, tp.x, dp.x);
        edge_math(b0, b1, an.y, tp.y, dp.y);
        edge_math(c0, c1, an.z, tp.z, dp.z);
        edge_math(d0, d1, an.w, tp.w, dp.w);
    } else {
        for (int k = e; k < E; k++) {
            int src = ei[k];
            edge_math(g_pack[2 * src], pk[8 * src + 4],
                      angles[k], transp[k], ei[(size_t)E + k]);
        }
    }
}

__global__ void out_kernel(const float* __restrict__ e1,
                           const float* __restrict__ e2,
                           float* __restrict__ out,
                           int V)
{
    int v = blockIdx.x * blockDim.x + threadIdx.x;
    if (v >= V) return;

    float4 a  = g_acc[v];
    float inv = 1.0f / fmaxf(a.w, 1.0f);
    float4 r1 = g_pack[2 * v + 1];     // {rpq, ds, s1, s2}

    float mag = a.x * inv + r1.y;
    float t1  = a.y * inv + r1.z;
    float t2  = a.z * inv + r1.w;
    float scale = __fdividef(2.0f, 1.0f + __expf(-mag));

    float s1 = t1 * scale, s2 = t2 * scale;
    out[3 * v + 0] = s1 * e1[3 * v + 0] + s2 * e2[3 * v + 0];
    out[3 * v + 1] = s1 * e1[3 * v + 1] + s2 * e2[3 * v + 1];
    out[3 * v + 2] = s1 * e1[3 * v + 2] + s2 * e2[3 * v + 2];
}

extern "C" void kernel_launch(void* const* d_in, const int* in_sizes, int n_in,
                              void* d_out, int out_size)
{
    const float* x        = (const float*)d_in[0];
    const int*   ei       = (const int*)d_in[1];
    const float* angles   = (const float*)d_in[2];
    const float* transp   = (const float*)d_in[3];
    const float* e1       = (const float*)d_in[4];
    const float* e2       = (const float*)d_in[5];
    const float* w_self0  = (const float*)d_in[6];
    const float* w_n00    = (const float*)d_in[7];
    const float* w_n10    = (const float*)d_in[8];
    const float* w_self11 = (const float*)d_in[9];
    const float* w_n01    = (const float*)d_in[10];
    const float* w_n11    = (const float*)d_in[11];
    float* out = (float*)d_out;

    int V = in_sizes[0] / 48;
    int E = in_sizes[2];

    feat_kernel<<<(V + FB - 1) / FB, FB>>>(x, w_self0, w_n00, w_n10,
                                           w_self11, w_n01, w_n11, V);
    int quads = (E + 3) / 4;
    edge_kernel<<<(quads + 255) / 256, 256>>>(ei, angles, transp, E);
    out_kernel<<<(V + 255) / 256, 256>>>(e1, e2, out, V);
}

// round 17
// speedup vs baseline: 1.2945x; 1.0163x over previous
#include <cuda_runtime.h>
#include <cuda_fp16.h>
#include <math.h>

#define MAXV 100000

// Packed per-node record: 2 float4 (32 B, one L2 sector, line-contiguous).
// rec0 = g_pack[2v]   = { d00 (f32), half2(da,db), half2(X,Y), half2(PA,PB) }
// rec1 = g_pack[2v+1] = { half2(RP,RQ), ds (f32), s1 (f32), s2 (f32) }
__device__ float4 g_pack[MAXV * 2];
__device__ float4 g_acc[MAXV];   // {sum m0, sum mv1, sum mv2, degree}

__device__ __forceinline__ float pack2(float a, float b) {
    __half2 h = __floats2half2_rn(a, b);
    return __uint_as_float(*reinterpret_cast<unsigned*>(&h));
}
__device__ __forceinline__ float2 unpack2(float f) {
    unsigned u = __float_as_uint(f);
    __half2 h = *reinterpret_cast<__half2*>(&u);
    return __half22float2(h);
}

#define FB 128            // nodes per feat block (= threads per block)
#define ROWP 49           // padded smem row stride; 49 mod 32 = 17 -> conflict-free

__global__ __launch_bounds__(FB, 8) void feat_kernel(
    const float* __restrict__ x,
    const float* __restrict__ w_self0,
    const float* __restrict__ w_n00,
    const float* __restrict__ w_n10,
    const float* __restrict__ w_self11,
    const float* __restrict__ w_n01,
    const float* __restrict__ w_n11,
    int V)
{
    // Vectorized weight tables: one LDS.128 fetches a whole channel's weights.
    __shared__ float4 swA[16];   // {w_n00[c], w_self0[c], w_n01[2c], w_n01[2c+1]}
    __shared__ float4 swB[16];   // {w_n10[2c], w_n10[2c+1], w_self11[2c], w_self11[2c+1]}
    __shared__ float4 swC[16];   // {w_n11[4c..4c+3]} = {p,q,r,s}
    __shared__ float  sx[FB * ROWP];

    int t = threadIdx.x;
    if (t < 16) {
        swA[t] = make_float4(w_n00[t], w_self0[t], w_n01[2 * t], w_n01[2 * t + 1]);
        swB[t] = make_float4(w_n10[2 * t], w_n10[2 * t + 1],
                             w_self11[2 * t], w_self11[2 * t + 1]);
        swC[t] = make_float4(w_n11[4 * t], w_n11[4 * t + 1],
                             w_n11[4 * t + 2], w_n11[4 * t + 3]);
    }

    int vb = blockIdx.x * FB;
    int nodes = min(FB, V - vb);
    const float4* xg = (const float4*)(x + (size_t)vb * 48);

    if (nodes == FB) {
        float4 r[12];
#pragma unroll
        for (int j = 0; j < 12; j++) r[j] = xg[t + j * FB];
#pragma unroll
        for (int j = 0; j < 12; j++) {
            int fl   = (t + j * FB) * 4;
            int node = fl / 48;             // float4 never crosses a row (48 % 4 == 0)
            int col  = fl - node * 48;
            float* d = &sx[node * ROWP + col];
            d[0] = r[j].x; d[1] = r[j].y; d[2] = r[j].z; d[3] = r[j].w;
        }
    } else {
        int nf4 = nodes * 12;
        for (int f = t; f < nf4; f += FB) {
            float4 val = xg[f];
            int fl   = f * 4;
            int node = fl / 48;
            int col  = fl - node * 48;
            float* d = &sx[node * ROWP + col];
            d[0] = val.x; d[1] = val.y; d[2] = val.z; d[3] = val.w;
        }
    }
    __syncthreads();

    int v = vb + t;
    if (v >= V) return;
    const float* xr = &sx[t * ROWP];

    float d00 = 0.f, da = 0.f, db = 0.f, ds = 0.f;
#pragma unroll
    for (int c = 0; c < 16; c++) {
        float x0 = xr[c];
        float4 w = swA[c];
        d00 = fmaf(x0, w.x, d00);
        ds  = fmaf(x0, w.y, ds);
        da  = fmaf(x0, w.z, da);
        db  = fmaf(x0, w.w, db);
    }

    float X = 0.f, Y = 0.f, PA = 0.f, PB = 0.f, RP = 0.f, RQ = 0.f, s1 = 0.f, s2 = 0.f;
#pragma unroll
    for (int c = 0; c < 16; c++) {
        float a = xr[16 + 2 * c];
        float b = xr[17 + 2 * c];
        float4 wB = swB[c];     // {wa, wb, sa, sb}
        float4 wC = swC[c];     // {p, q, r, s}
        X  = fmaf(a, wB.x, fmaf(b, wB.y, X));
        Y  = fmaf(a, wB.y, fmaf(-b, wB.x, Y));
        s1 = fmaf(a, wB.z, fmaf(-b, wB.w, s1));
        s2 = fmaf(b, wB.z, fmaf(a, wB.w, s2));
        PA = fmaf(a, wC.x, fmaf(-b, wC.y, PA));
        PB = fmaf(b, wC.x, fmaf(a, wC.y, PB));
        RP = fmaf(a, wC.z, fmaf(b, wC.w, RP));
        RQ = fmaf(a, wC.w, fmaf(-b, wC.z, RQ));
    }

    g_pack[2 * v + 0] = make_float4(d00, pack2(da, db), pack2(X, Y), pack2(PA, PB));
    g_pack[2 * v + 1] = make_float4(pack2(RP, RQ), ds, s1, s2);
    g_acc[v] = make_float4(0.f, 0.f, 0.f, 0.f);
}

__device__ __forceinline__ void edge_math(float4 r0, float rpq_packed,
                                          float ang, float tr, int dst)
{
    float st, ct, sg, cg;
    __sincosf(ang, &st, &ct);
    __sincosf(tr,  &sg, &cg);
    float c2t = ct * ct - st * st;
    float s2t = 2.f * st * ct;

    float2 dab = unpack2(r0.y);
    float2 xy  = unpack2(r0.z);
    float2 pab = unpack2(r0.w);
    float2 rpq = unpack2(rpq_packed);

    float d1 = cg * xy.x + sg * xy.y;
    float d2 = sg * xy.x - cg * xy.y;
    float A  = cg * pab.x - sg * pab.y;
    float B  = sg * pab.x + cg * pab.y;
    float P  = cg * rpq.x + sg * rpq.y;
    float Q  = sg * rpq.x - cg * rpq.y;

    float m0  = r0.x + ct * d1 + st * d2;
    float mv1 = dab.x * ct - dab.y * st + A + c2t * P + s2t * Q;
    float mv2 = dab.x * st + dab.y * ct + B + s2t * P - c2t * Q;

    float4* addr = &g_acc[dst];
    asm volatile("red.global.add.v4.f32 [%0], {%1, %2, %3, %4};"
                 :: "l"(addr), "f"(m0), "f"(mv1), "f"(mv2), "f"(1.0f)
                 : "memory");
}

// Pair-cooperative edge kernel: each warp handles 64 edges (2 rounds of 32).
// In each round, lane pair (2k, 2k+1) loads the two 16B halves of the SAME
// 32B node record (one 128B line -> 16 lines/instr instead of 32), then
// SHFL.bfly(1) redistributes so every lane owns one full edge.
__global__ void edge_kernel(const int* __restrict__ ei,
                            const float* __restrict__ angles,
                            const float* __restrict__ transp,
                            int E)
{
    int gtid = blockIdx.x * blockDim.x + threadIdx.x;
    int warp = gtid >> 5;
    int lane = gtid & 31;
    int k    = lane >> 1;
    int odd  = lane & 1;
    int base = warp * 64;
    if (base >= E) return;

    if (base + 64 <= E) {
        // src indices (permuted within 32 -> still 1-2 lines per instr)
        int sA0 = ei[base + k];
        int sB0 = ei[base + 16 + k];
        int sA1 = ei[base + 32 + k];
        int sB1 = ei[base + 48 + k];

        int me0 = base + (odd ? 16 + k : k);
        int me1 = base + 32 + (odd ? 16 + k : k);

        float ang0 = angles[me0], trp0 = transp[me0];
        float ang1 = angles[me1], trp1 = transp[me1];
        int   dst0 = ei[E + me0], dst1 = ei[E + me1];

        // cooperative record loads: even lane -> rec0, odd lane -> rec1
        float4 A0 = g_pack[2 * sA0 + odd];
        float4 B0 = g_pack[2 * sB0 + odd];
        float4 A1 = g_pack[2 * sA1 + odd];
        float4 B1 = g_pack[2 * sB1 + odd];

        // round 0 redistribution
        float pa0 = __shfl_xor_sync(0xffffffffu, A0.x, 1);  // partner rec1.x -> even
        float4 pB0;
        pB0.x = __shfl_xor_sync(0xffffffffu, B0.x, 1);
        pB0.y = __shfl_xor_sync(0xffffffffu, B0.y, 1);
        pB0.z = __shfl_xor_sync(0xffffffffu, B0.z, 1);
        pB0.w = __shfl_xor_sync(0xffffffffu, B0.w, 1);      // partner rec0 -> odd
        float4 r00 = odd ? pB0 : A0;
        float  q0  = odd ? B0.x : pa0;

        // round 1 redistribution
        float pa1 = __shfl_xor_sync(0xffffffffu, A1.x, 1);
        float4 pB1;
        pB1.x = __shfl_xor_sync(0xffffffffu, B1.x, 1);
        pB1.y = __shfl_xor_sync(0xffffffffu, B1.y, 1);
        pB1.z = __shfl_xor_sync(0xffffffffu, B1.z, 1);
        pB1.w = __shfl_xor_sync(0xffffffffu, B1.w, 1);
        float4 r01 = odd ? pB1 : A1;
        float  q1  = odd ? B1.x : pa1;

        edge_math(r00, q0, ang0, trp0, dst0);
        edge_math(r01, q1, ang1, trp1, dst1);
    } else {
        // tail warp: scalar fallback
        const float* pk = (const float*)g_pack;
        for (int off = lane; off < 64; off += 32) {
            int e = base + off;
            if (e >= E) break;
            int src = ei[e];
            edge_math(g_pack[2 * src], pk[8 * src + 4],
                      angles[e], transp[e], ei[E + e]);
        }
    }
}

__global__ void out_kernel(const float* __restrict__ e1,
                           const float* __restrict__ e2,
                           float* __restrict__ out,
                           int V)
{
    int v = blockIdx.x * blockDim.x + threadIdx.x;
    if (v >= V) return;

    float4 a  = g_acc[v];
    float inv = 1.0f / fmaxf(a.w, 1.0f);
    float4 r1 = g_pack[2 * v + 1];     // {rpq, ds, s1, s2}

    float mag = a.x * inv + r1.y;
    float t1  = a.y * inv + r1.z;
    float t2  = a.z * inv + r1.w;
    float scale = __fdividef(2.0f, 1.0f + __expf(-mag));

    float s1 = t1 * scale, s2 = t2 * scale;
    out[3 * v + 0] = s1 * e1[3 * v + 0] + s2 * e2[3 * v + 0];
    out[3 * v + 1] = s1 * e1[3 * v + 1] + s2 * e2[3 * v + 1];
    out[3 * v + 2] = s1 * e1[3 * v + 2] + s2 * e2[3 * v + 2];
}

extern "C" void kernel_launch(void* const* d_in, const int* in_sizes, int n_in,
                              void* d_out, int out_size)
{
    const float* x        = (const float*)d_in[0];
    const int*   ei       = (const int*)d_in[1];
    const float* angles   = (const float*)d_in[2];
    const float* transp   = (const float*)d_in[3];
    const float* e1       = (const float*)d_in[4];
    const float* e2       = (const float*)d_in[5];
    const float* w_self0  = (const float*)d_in[6];
    const float* w_n00    = (const float*)d_in[7];
    const float* w_n10    = (const float*)d_in[8];
    const float* w_self11 = (const float*)d_in[9];
    const float* w_n01    = (const float*)d_in[10];
    const float* w_n11    = (const float*)d_in[11];
    float* out = (float*)d_out;

    int V = in_sizes[0] / 48;
    int E = in_sizes[2];

    feat_kernel<<<(V + FB - 1) / FB, FB>>>(x, w_self0, w_n00, w_n10,
                                           w_self11, w_n01, w_n11, V);
    int nwarps   = (E + 63) / 64;
    int nthreads = nwarps * 32;
    edge_kernel<<<(nthreads + 255) / 256, 256>>>(ei, angles, transp, E);
    out_kernel<<<(V + 255) / 256, 256>>>(e1, e2, out, V);
}